// round 17
// baseline (speedup 1.0000x reference)
#include <cuda_runtime.h>
#include <cuda_bf16.h>

// IndRNN, 2 layers, warp-specialized:
//   layer i: h_t = relu(x_t + h_{t-1} * w_i)   (elementwise over (b,h))
//
// R15 profile: 1 warp/SMSP -> serial fma/relu chain + memory stalls fully
// exposed (issue 13.6%, DRAM 47.7%). Fix: split layers across two thread
// roles in one block. A-threads: gmem load -> layer1 -> smem ring (STS).
// B-threads: smem ring (LDS) -> layer2 -> gmem store. B lags A by one
// CHUNK, double-buffered ring, __syncthreads between phases. 8 warps/SM
// (2 per SMSP) so the two 8-cyc/step recurrence chains and the LDG/STG
// streams hide each other.

#define TT 2048
#define BB 32
#define HH 512
#define BH (BB * HH)

#define CPB   128                 // chains per block
#define CHUNK 128                 // timesteps per phase
#define NCHUNK (TT / CHUNK)       // 16
#define RING_ELEMS (2 * CHUNK * CPB)
#define RING_BYTES (RING_ELEMS * 4)   // 128 KB dynamic smem

__device__ __forceinline__ float relu_fma(float h, float w, float x) {
    return fmaxf(fmaf(h, w, x), 0.0f);
}

__global__ void __launch_bounds__(2 * CPB, 1)
indrnn_ws(const float* __restrict__ x,
          const float* __restrict__ w,
          const float* __restrict__ h0,
          float* __restrict__ out) {
    extern __shared__ float ring[];   // [2][CHUNK][CPB]

    const int  lane = threadIdx.x & (CPB - 1);
    const bool isA  = threadIdx.x < CPB;       // warps 0-3 = A, 4-7 = B
    const int  idx  = blockIdx.x * CPB + lane; // (b,h) chain id
    const int  h    = idx & (HH - 1);

    if (isA) {
        // ---- Producer: layer 1 (gmem -> smem ring) ----
        const float w1 = w[h];
        float h1 = h0[idx];
        const float* xp = x + idx;

        constexpr int U    = 16;
        constexpr int PIPE = 4;
        constexpr int STEP = U * PIPE;    // 64
        static_assert(CHUNK % STEP == 0, "");

        float buf[PIPE][U];
#pragma unroll
        for (int p = 0; p < PIPE; ++p)
#pragma unroll
            for (int i = 0; i < U; ++i)
                buf[p][i] = __ldcs(xp + (size_t)(p * U + i) * BH);

#pragma unroll 1
        for (int ph = 0; ph <= NCHUNK; ++ph) {
            if (ph < NCHUNK) {
                const int base = ph * CHUNK;
                float* s = ring + (ph & 1) * (CHUNK * CPB) + lane;
#pragma unroll
                for (int t0 = 0; t0 < CHUNK; t0 += STEP) {
#pragma unroll
                    for (int p = 0; p < PIPE; ++p) {
                        // Prefetch one STEP (64 steps) ahead; loads cross the
                        // barrier safely (register-resident gmem loads).
                        const int tl = base + t0 + STEP + p * U;
                        const bool live = (tl < TT);
                        float nxt[U];
#pragma unroll
                        for (int i = 0; i < U; ++i)
                            nxt[i] = live ? __ldcs(xp + (size_t)(tl + i) * BH)
                                          : 0.0f;

                        const int tb = t0 + p * U;
#pragma unroll
                        for (int i = 0; i < U; ++i) {
                            h1 = relu_fma(h1, w1, buf[p][i]);
                            s[(tb + i) * CPB] = h1;   // STS, conflict-free
                        }
#pragma unroll
                        for (int i = 0; i < U; ++i) buf[p][i] = nxt[i];
                    }
                }
            }
            __syncthreads();
        }
    } else {
        // ---- Consumer: layer 2 (smem ring -> gmem) ----
        const float w2 = w[HH + h];
        float h2 = h0[BH + idx];
        float* op = out + idx;

        constexpr int U = 16;

#pragma unroll 1
        for (int ph = 0; ph <= NCHUNK; ++ph) {
            if (ph >= 1) {
                const int base = (ph - 1) * CHUNK;
                const float* s =
                    ring + ((ph - 1) & 1) * (CHUNK * CPB) + lane;
#pragma unroll
                for (int t0 = 0; t0 < CHUNK; t0 += U) {
                    float v[U];
#pragma unroll
                    for (int i = 0; i < U; ++i)
                        v[i] = s[(t0 + i) * CPB];     // LDS, batched
#pragma unroll
                    for (int i = 0; i < U; ++i) {
                        h2 = relu_fma(h2, w2, v[i]);
                        __stcs(op + (size_t)(base + t0 + i) * BH, h2);
                    }
                }
            }
            __syncthreads();
        }
    }
}

// Generic fallback for unexpected shapes (fused 2-layer, one thread/chain).
__global__ void indrnn_fused_generic(const float* __restrict__ x,
                                     const float* __restrict__ w,
                                     const float* __restrict__ h0,
                                     float* __restrict__ out,
                                     int T, int B, int H) {
    const int bh = B * H;
    for (int idx = blockIdx.x * blockDim.x + threadIdx.x; idx < bh;
         idx += gridDim.x * blockDim.x) {
        const int hc = idx % H;
        const float w1 = w[hc];
        const float w2 = w[H + hc];
        float h1 = h0[idx];
        float h2 = h0[bh + idx];
        const float* xp = x + idx;
        float*       op = out + idx;
        for (int t = 0; t < T; ++t) {
            h1 = relu_fma(h1, w1, __ldcs(xp + (size_t)t * bh));
            h2 = relu_fma(h2, w2, h1);
            __stcs(op + (size_t)t * bh, h2);
        }
    }
}

extern "C" void kernel_launch(void* const* d_in, const int* in_sizes, int n_in,
                              void* d_out, int out_size) {
    const float* x  = (const float*)d_in[0];  // [T, B, H]
    const float* w  = (const float*)d_in[1];  // [2, H]
    const float* h0 = (const float*)d_in[2];  // [2, B, H]
    float* out = (float*)d_out;               // [T, B, H]

    const int H = in_sizes[1] / 2;
    const int B = (H > 0) ? in_sizes[2] / (2 * H) : 0;
    const int bh = B * H;
    const int T = (bh > 0) ? in_sizes[0] / bh : 0;

    if (T == TT && B == BB && H == HH) {
        // 128 KB dynamic smem needs an explicit opt-in (host-side attribute,
        // not a stream op — safe under graph capture; idempotent per call).
        cudaFuncSetAttribute(indrnn_ws,
                             cudaFuncAttributeMaxDynamicSharedMemorySize,
                             RING_BYTES);
        indrnn_ws<<<BH / CPB, 2 * CPB, RING_BYTES>>>(x, w, h0, out);
    } else {
        int threads = 128;
        int blocks = (bh + threads - 1) / threads;
        if (blocks < 1) blocks = 1;
        indrnn_fused_generic<<<blocks, threads>>>(x, w, h0, out, T, B, H);
    }
}